// round 14
// baseline (speedup 1.0000x reference)
#include <cuda_runtime.h>
#include <cuda_fp16.h>
#include <cstdint>

#define NN 50000
#define FF 64
#define EE 800000
#define SCAN_BLOCKS ((NN + 255) / 256)   // 196
#define EX_CAP 64
#define XS_BYTES (128 * 72 * 2)
#define WS_BYTES (256 * 72 * 2)
#define GEMM_SMEM (2 * XS_BYTES + 2 * WS_BYTES)   // 110592

// Scratch (static __device__ — zero-initialized at load; kernels restore their
// scratch to zero each execution so graph replays are deterministic)
__device__ float        g_q[(size_t)NN * 128];    // [N][h*64+f]
__device__ float        g_k[(size_t)NN * 128];
__device__ int          g_hist[NN];
__device__ int          g_start[NN + 1];
__device__ unsigned int g_state[SCAN_BLOCKS];     // lookback: (sum<<2)|status
__device__ int          g_cursor[NN];
__device__ int2         g_sedge[EE];              // (col, orig edge id) row-sorted
__device__ float        g_ex2[(size_t)EE * 2];    // fallback exp storage (deg > EX_CAP)

#define MMA16816(d, a0, a1, a2, a3, b0, b1) \
    asm volatile("mma.sync.aligned.m16n8k16.row.col.f32.f16.f16.f32 " \
        "{%0,%1,%2,%3}, {%4,%5,%6,%7}, {%8,%9}, {%0,%1,%2,%3};" \
        : "+f"((d)[0]), "+f"((d)[1]), "+f"((d)[2]), "+f"((d)[3]) \
        : "r"(a0), "r"(a1), "r"(a2), "r"(a3), "r"(b0), "r"(b1))

// ---------------- counting sort of edges by row (proven) ----------------

__global__ void hist_kernel(const int4* __restrict__ row4) {
    int i = blockIdx.x * blockDim.x + threadIdx.x;
    if (i < EE / 4) {
        int4 r = __ldg(row4 + i);
        atomicAdd(&g_hist[r.x], 1);
        atomicAdd(&g_hist[r.y], 1);
        atomicAdd(&g_hist[r.z], 1);
        atomicAdd(&g_hist[r.w], 1);
    }
}

// Single-pass exclusive scan with decoupled lookback (packed state word).
// Also resets g_hist; g_state is reset by scatter_kernel (after all readers).
__global__ void scan_lb_kernel() {
    __shared__ int sh[256];
    __shared__ int s_exc;
    const int t = threadIdx.x;
    const int bid = blockIdx.x;
    const int i = bid * 256 + t;
    int v = 0;
    if (i < NN) { v = g_hist[i]; g_hist[i] = 0; }
    sh[t] = v;
    __syncthreads();
#pragma unroll
    for (int off = 1; off < 256; off <<= 1) {
        int u = (t >= off) ? sh[t - off] : 0;
        __syncthreads();
        sh[t] += u;
        __syncthreads();
    }
    const int blockAgg = sh[255];

    if (t == 0) {
        if (bid == 0) {
            atomicExch(&g_state[0], ((unsigned)blockAgg << 2) | 2u);
            s_exc = 0;
        } else {
            atomicExch(&g_state[bid], ((unsigned)blockAgg << 2) | 1u);
            int exc = 0;
            int p = bid - 1;
            while (true) {
                unsigned st;
                do { st = atomicOr(&g_state[p], 0u); } while ((st & 3u) == 0u);
                exc += (int)(st >> 2);
                if ((st & 3u) == 2u) break;
                p--;
            }
            atomicExch(&g_state[bid], ((unsigned)(exc + blockAgg) << 2) | 2u);
            s_exc = exc;
        }
    }
    __syncthreads();
    const int base = s_exc;
    if (i < NN) {
        int s = sh[t] - v + base;   // exclusive
        g_start[i] = s;
        g_cursor[i] = s;
    }
    if (i == 0) g_start[NN] = EE;
}

__global__ void scatter_kernel(const int* __restrict__ row, const int* __restrict__ col) {
    if (blockIdx.x == 0 && threadIdx.x < SCAN_BLOCKS) g_state[threadIdx.x] = 0u;
    int e = blockIdx.x * blockDim.x + threadIdx.x;
    if (e >= EE) return;
    int r = row[e];
    int pos = atomicAdd(&g_cursor[r], 1);
    g_sedge[pos] = make_int2(col[e], e);
}

// ---------------- QK projection GEMM (tensor cores, fp16 split) ----------------
// D = xhi*Whi + xhi*Wlo + xlo*Whi (fp16 operands, fp32 acc).
__global__ void __launch_bounds__(512) gemm_qk_kernel(const float* __restrict__ x,
                                                      const float* __restrict__ W,
                                                      const float* __restrict__ b) {
    extern __shared__ char sm_raw[];
    __half* xs_h = (__half*)sm_raw;                       // [128][72]
    __half* xs_l = (__half*)(sm_raw + XS_BYTES);
    __half* ws_h = (__half*)(sm_raw + 2 * XS_BYTES);      // [256][72] = W^T
    __half* ws_l = (__half*)(sm_raw + 2 * XS_BYTES + WS_BYTES);
    const int tid = threadIdx.x;
    const int n0 = blockIdx.x * 128;

#pragma unroll
    for (int i = 0; i < 4; i++) {
        int lin = tid + i * 512;
        int r = lin >> 4, k4 = lin & 15;
        int n = n0 + r;
        float4 v = make_float4(0.f, 0.f, 0.f, 0.f);
        if (n < NN) v = __ldg((const float4*)x + (size_t)n * 16 + k4);
        float cc[4] = {v.x, v.y, v.z, v.w};
#pragma unroll
        for (int j = 0; j < 4; j++) {
            int k = k4 * 4 + j;
            __half h = __float2half_rn(cc[j]);
            float lo = cc[j] - __half2float(h);
            xs_h[r * 72 + k] = h;
            xs_l[r * 72 + k] = __float2half_rn(lo);
        }
    }
#pragma unroll
    for (int i = 0; i < 8; i++) {
        int lin = tid + i * 512;
        int k = lin >> 6, nq = lin & 63;
        float4 v = __ldg((const float4*)W + lin);
        float cc[4] = {v.x, v.y, v.z, v.w};
#pragma unroll
        for (int j = 0; j < 4; j++) {
            int n = nq * 4 + j;
            __half h = __float2half_rn(cc[j]);
            float lo = cc[j] - __half2float(h);
            ws_h[n * 72 + k] = h;
            ws_l[n * 72 + k] = __float2half_rn(lo);
        }
    }
    __syncthreads();

    const int warp = tid >> 5, lane = tid & 31;
    const int wm = warp >> 1, wn = warp & 1;
    const int g = lane >> 2, t = lane & 3;
    const int rowb = wm * 16;

    float acc[16][4];
#pragma unroll
    for (int nt = 0; nt < 16; nt++) {
        int col0 = wn * 128 + nt * 8 + 2 * t;
        float2 bb = *(const float2*)(b + col0);
        acc[nt][0] = bb.x; acc[nt][1] = bb.y;
        acc[nt][2] = bb.x; acc[nt][3] = bb.y;
    }

#pragma unroll
    for (int ks = 0; ks < 4; ks++) {
        const int ka = ks * 16 + 2 * t;
        const int ra = (rowb + g) * 72, rb = (rowb + g + 8) * 72;
        uint32_t ah0 = *(const uint32_t*)&xs_h[ra + ka];
        uint32_t ah1 = *(const uint32_t*)&xs_h[rb + ka];
        uint32_t ah2 = *(const uint32_t*)&xs_h[ra + ka + 8];
        uint32_t ah3 = *(const uint32_t*)&xs_h[rb + ka + 8];
        uint32_t al0 = *(const uint32_t*)&xs_l[ra + ka];
        uint32_t al1 = *(const uint32_t*)&xs_l[rb + ka];
        uint32_t al2 = *(const uint32_t*)&xs_l[ra + ka + 8];
        uint32_t al3 = *(const uint32_t*)&xs_l[rb + ka + 8];
#pragma unroll
        for (int nt = 0; nt < 16; nt++) {
            int n = (wn * 128 + nt * 8 + g) * 72;
            uint32_t bh0 = *(const uint32_t*)&ws_h[n + ka];
            uint32_t bh1 = *(const uint32_t*)&ws_h[n + ka + 8];
            uint32_t bl0 = *(const uint32_t*)&ws_l[n + ka];
            uint32_t bl1 = *(const uint32_t*)&ws_l[n + ka + 8];
            MMA16816(acc[nt], ah0, ah1, ah2, ah3, bh0, bh1);
            MMA16816(acc[nt], ah0, ah1, ah2, ah3, bl0, bl1);
            MMA16816(acc[nt], al0, al1, al2, al3, bh0, bh1);
        }
    }

    const int nr0 = n0 + rowb + g;
    const int nr1 = nr0 + 8;
#pragma unroll
    for (int nt = 0; nt < 16; nt++) {
        int cl = nt * 8 + 2 * t;
        float* outbase = ((cl >> 6) & 1) ? g_k : g_q;
        int f = cl & 63;
        size_t off = (size_t)wn * 64 + f;
        if (nr0 < NN)
            *(float2*)(outbase + (size_t)nr0 * 128 + off) = make_float2(acc[nt][0], acc[nt][1]);
        if (nr1 < NN)
            *(float2*)(outbase + (size_t)nr1 * 128 + off) = make_float2(acc[nt][2], acc[nt][3]);
    }
}

// ---------------- fused edge scores + softmax + output ----------------
// One warp per row, 8-lane groups: group (h, esl) handles head h of edges
// (pos+esl, pos+2+esl). Lane covers 8 contiguous features (2 LDG.128).
// 4-edge batch = 4 LDG.128 + 3-stage reduce serving 4 sums per shuffle pass;
// group leaders (lanes 0,8,16,24) hold distinct sums -> distributed exp with
// no select chain. D0 = d@0 + d@16, D1 = d@8 + d@24.
__global__ void __launch_bounds__(256) edge_row_kernel(float* __restrict__ out) {
    __shared__ float2 exs[8][EX_CAP + 4];
    __shared__ int2   sse[8][EX_CAP];
    const int warp = threadIdx.x >> 5;
    const int lane = threadIdx.x & 31;
    const int r = blockIdx.x * 8 + warp;
    if (r >= NN) return;

    const int s0 = g_start[r];
    const int s1 = g_start[r + 1];
    const int deg = s1 - s0;
    if (deg == 0) return;

    const int gl  = lane & 7;              // lane within group
    const int grp = lane >> 3;             // 0..3
    const int h   = grp & 1;               // head
    const int esl = grp >> 1;              // edge-slot within batch
    const bool leader = (gl == 0);

    const float4* qb = (const float4*)(g_q + (size_t)r * 128 + h * 64 + gl * 8);
    const float4 qa = qb[0], qc = qb[1];
    const float* kp = g_k;
    float d = 0.0f;

    if (deg <= EX_CAP) {
        for (int j = lane; j < deg; j += 32) sse[warp][j] = g_sedge[s0 + j];
        __syncwarp();

        int pos = 0;
        const int qend = deg & ~3;
        for (; pos < qend; pos += 4) {
            int cA = sse[warp][pos + esl].x;
            int cB = sse[warp][pos + 2 + esl].x;
            const float4* kA = (const float4*)(kp + (size_t)cA * 128 + h * 64 + gl * 8);
            const float4* kB = (const float4*)(kp + (size_t)cB * 128 + h * 64 + gl * 8);
            float4 a0 = __ldg(kA), a1 = __ldg(kA + 1);
            float4 b0 = __ldg(kB), b1 = __ldg(kB + 1);
            float pA = qa.x * a0.x + qa.y * a0.y + qa.z * a0.z + qa.w * a0.w
                     + qc.x * a1.x + qc.y * a1.y + qc.z * a1.z + qc.w * a1.w;
            float pB = qa.x * b0.x + qa.y * b0.y + qa.z * b0.z + qa.w * b0.w
                     + qc.x * b1.x + qc.y * b1.y + qc.z * b1.z + qc.w * b1.w;
#pragma unroll
            for (int off = 4; off >= 1; off >>= 1) {
                pA += __shfl_xor_sync(0xffffffffu, pA, off);
                pB += __shfl_xor_sync(0xffffffffu, pB, off);
            }
            if (leader) {
                float vA = __expf(pA);
                float vB = __expf(pB);
                ((float*)&exs[warp][pos + esl])[h] = vA;
                ((float*)&exs[warp][pos + 2 + esl])[h] = vB;
                d += vA + vB;
            }
        }
        for (; pos < deg; pos++) {   // remainder: all groups same edge, esl dup
            int c0 = sse[warp][pos].x;
            const float4* kk = (const float4*)(kp + (size_t)c0 * 128 + h * 64 + gl * 8);
            float4 a0 = __ldg(kk), a1 = __ldg(kk + 1);
            float p = qa.x * a0.x + qa.y * a0.y + qa.z * a0.z + qa.w * a0.w
                    + qc.x * a1.x + qc.y * a1.y + qc.z * a1.z + qc.w * a1.w;
#pragma unroll
            for (int off = 4; off >= 1; off >>= 1)
                p += __shfl_xor_sync(0xffffffffu, p, off);
            if (leader && esl == 0) {
                float v = __expf(p);
                ((float*)&exs[warp][pos])[h] = v;
                d += v;
            }
        }
        // head0 partials on lanes 0,16; head1 on lanes 8,24
        float D0 = __shfl_sync(0xffffffffu, d, 0) + __shfl_sync(0xffffffffu, d, 16);
        float D1 = __shfl_sync(0xffffffffu, d, 8) + __shfl_sync(0xffffffffu, d, 24);
        float i0 = 0.5f / D0, i1 = 0.5f / D1;
        __syncwarp();
        for (int j = lane; j < deg; j += 32) {
            float2 e = exs[warp][j];
            out[sse[warp][j].y] = e.x * i0 + e.y * i1;
        }
    } else {
        // fallback (deg > 64; unreachable for this input)
        for (int posg = s0; posg < s1; posg++) {
            int c0 = g_sedge[posg].x;
            const float4* kk = (const float4*)(kp + (size_t)c0 * 128 + h * 64 + gl * 8);
            float4 a0 = __ldg(kk), a1 = __ldg(kk + 1);
            float p = qa.x * a0.x + qa.y * a0.y + qa.z * a0.z + qa.w * a0.w
                    + qc.x * a1.x + qc.y * a1.y + qc.z * a1.z + qc.w * a1.w;
#pragma unroll
            for (int off = 4; off >= 1; off >>= 1)
                p += __shfl_xor_sync(0xffffffffu, p, off);
            if (leader && esl == 0) {
                float v = __expf(p);
                g_ex2[2 * (size_t)posg + h] = v;
                d += v;
            }
        }
        float D0 = __shfl_sync(0xffffffffu, d, 0);
        float D1 = __shfl_sync(0xffffffffu, d, 8);
        float i0 = 0.5f / D0, i1 = 0.5f / D1;
        __syncwarp();
        for (int j = lane; j < deg; j += 32) {
            float2 e = *(const float2*)(g_ex2 + 2 * (size_t)(s0 + j));
            out[g_sedge[s0 + j].y] = e.x * i0 + e.y * i1;
        }
    }
}

extern "C" void kernel_launch(void* const* d_in, const int* in_sizes, int n_in,
                              void* d_out, int out_size) {
    const float* x    = (const float*)d_in[0];
    const float* W_qk = (const float*)d_in[1];
    const float* b_qk = (const float*)d_in[2];
    const int*   ei   = (const int*)d_in[3];   // [2, E] row-major
    const int* row = ei;
    const int* col = ei + EE;
    float* out = (float*)d_out;

    cudaFuncSetAttribute(gemm_qk_kernel,
                         cudaFuncAttributeMaxDynamicSharedMemorySize, GEMM_SMEM);

    // Fork: GEMM first (submission priority) on s2, overlapping the sort chain.
    cudaStream_t s2;
    cudaEvent_t evFork, evJoin;
    cudaStreamCreateWithFlags(&s2, cudaStreamNonBlocking);
    cudaEventCreateWithFlags(&evFork, cudaEventDisableTiming);
    cudaEventCreateWithFlags(&evJoin, cudaEventDisableTiming);

    cudaEventRecord(evFork, 0);
    cudaStreamWaitEvent(s2, evFork, 0);

    gemm_qk_kernel<<<(NN + 127) / 128, 512, GEMM_SMEM, s2>>>(x, W_qk, b_qk);
    cudaEventRecord(evJoin, s2);

    hist_kernel<<<(EE / 4 + 255) / 256, 256>>>((const int4*)row);
    scan_lb_kernel<<<SCAN_BLOCKS, 256>>>();
    scatter_kernel<<<(EE + 255) / 256, 256>>>(row, col);

    cudaStreamWaitEvent(0, evJoin, 0);
    edge_row_kernel<<<(NN + 7) / 8, 256>>>(out);
}

// round 16
// speedup vs baseline: 1.1791x; 1.1791x over previous
#include <cuda_runtime.h>
#include <cuda_fp16.h>
#include <cstdint>

#define NN 50000
#define FF 64
#define EE 800000
#define SCAN_BLOCKS ((NN + 255) / 256)   // 196
#define EX_CAP 128
#define XS_BYTES (128 * 72 * 2)
#define WS_BYTES (256 * 72 * 2)
#define GEMM_SMEM (2 * XS_BYTES + 2 * WS_BYTES)   // 110592

// Scratch (static __device__ — zero-initialized at load; kernels restore their
// scratch to zero each execution so graph replays are deterministic)
__device__ float        g_q[(size_t)NN * 128];    // [N][h*64+f]
__device__ float        g_k[(size_t)NN * 128];
__device__ int          g_hist[NN];
__device__ int          g_start[NN + 1];
__device__ unsigned int g_state[SCAN_BLOCKS];     // lookback: (sum<<2)|status
__device__ int          g_cursor[NN];
__device__ int2         g_sedge[EE];              // (col, orig edge id) row-sorted
__device__ float        g_ex2[(size_t)EE * 2];    // fallback exp storage (deg > EX_CAP)
// pre-converted fp16 hi/lo operands (written each run by xconv/wconv)
__device__ __half       g_xh[(size_t)NN * 64];
__device__ __half       g_xl[(size_t)NN * 64];
__device__ __half       g_wTh[256 * 72];          // W^T padded [n][k]
__device__ __half       g_wTl[256 * 72];

#define MMA16816(d, a0, a1, a2, a3, b0, b1) \
    asm volatile("mma.sync.aligned.m16n8k16.row.col.f32.f16.f16.f32 " \
        "{%0,%1,%2,%3}, {%4,%5,%6,%7}, {%8,%9}, {%0,%1,%2,%3};" \
        : "+f"((d)[0]), "+f"((d)[1]), "+f"((d)[2]), "+f"((d)[3]) \
        : "r"(a0), "r"(a1), "r"(a2), "r"(a3), "r"(b0), "r"(b1))

// ---------------- counting sort of edges by row (proven) ----------------

__global__ void hist_kernel(const int4* __restrict__ row4) {
    int i = blockIdx.x * blockDim.x + threadIdx.x;
    if (i < EE / 4) {
        int4 r = __ldg(row4 + i);
        atomicAdd(&g_hist[r.x], 1);
        atomicAdd(&g_hist[r.y], 1);
        atomicAdd(&g_hist[r.z], 1);
        atomicAdd(&g_hist[r.w], 1);
    }
}

__global__ void scan_lb_kernel() {
    __shared__ int sh[256];
    __shared__ int s_exc;
    const int t = threadIdx.x;
    const int bid = blockIdx.x;
    const int i = bid * 256 + t;
    int v = 0;
    if (i < NN) { v = g_hist[i]; g_hist[i] = 0; }
    sh[t] = v;
    __syncthreads();
#pragma unroll
    for (int off = 1; off < 256; off <<= 1) {
        int u = (t >= off) ? sh[t - off] : 0;
        __syncthreads();
        sh[t] += u;
        __syncthreads();
    }
    const int blockAgg = sh[255];
    if (t == 0) {
        if (bid == 0) {
            atomicExch(&g_state[0], ((unsigned)blockAgg << 2) | 2u);
            s_exc = 0;
        } else {
            atomicExch(&g_state[bid], ((unsigned)blockAgg << 2) | 1u);
            int exc = 0;
            int p = bid - 1;
            while (true) {
                unsigned st;
                do { st = atomicOr(&g_state[p], 0u); } while ((st & 3u) == 0u);
                exc += (int)(st >> 2);
                if ((st & 3u) == 2u) break;
                p--;
            }
            atomicExch(&g_state[bid], ((unsigned)(exc + blockAgg) << 2) | 2u);
            s_exc = exc;
        }
    }
    __syncthreads();
    const int base = s_exc;
    if (i < NN) {
        int s = sh[t] - v + base;
        g_start[i] = s;
        g_cursor[i] = s;
    }
    if (i == 0) g_start[NN] = EE;
}

__global__ void scatter_kernel(const int* __restrict__ row, const int* __restrict__ col) {
    if (blockIdx.x == 0 && threadIdx.x < SCAN_BLOCKS) g_state[threadIdx.x] = 0u;
    int e = blockIdx.x * blockDim.x + threadIdx.x;
    if (e >= EE) return;
    int r = row[e];
    int pos = atomicAdd(&g_cursor[r], 1);
    g_sedge[pos] = make_int2(col[e], e);
}

// ---------------- one-time operand conversion (hoisted out of gemm) ----------------

// x -> hi/lo halves, [N][64] layout. 4 floats per thread.
__global__ void __launch_bounds__(256) xconv_kernel(const float* __restrict__ x) {
    int i = blockIdx.x * blockDim.x + threadIdx.x;   // float4 index
    if (i >= NN * 16) return;
    float4 v = __ldg((const float4*)x + i);
    float f[4] = {v.x, v.y, v.z, v.w};
    ushort2 hi2[2], lo2[2];
#pragma unroll
    for (int j = 0; j < 2; j++) {
        __half h0 = __float2half_rn(f[2 * j]);
        __half h1 = __float2half_rn(f[2 * j + 1]);
        __half l0 = __float2half_rn(f[2 * j] - __half2float(h0));
        __half l1 = __float2half_rn(f[2 * j + 1] - __half2float(h1));
        hi2[j] = make_ushort2(__half_as_ushort(h0), __half_as_ushort(h1));
        lo2[j] = make_ushort2(__half_as_ushort(l0), __half_as_ushort(l1));
    }
    *(uint2*)((__half*)g_xh + (size_t)i * 4) = *(uint2*)hi2;
    *(uint2*)((__half*)g_xl + (size_t)i * 4) = *(uint2*)lo2;
}

// W[64][256] -> transposed padded hi/lo [256][72]. One element per thread.
__global__ void __launch_bounds__(256) wconv_kernel(const float* __restrict__ W) {
    int i = blockIdx.x * blockDim.x + threadIdx.x;
    if (i >= 64 * 256) return;
    int k = i >> 8, n = i & 255;
    float f = __ldg(W + k * 256 + n);
    __half h = __float2half_rn(f);
    __half l = __float2half_rn(f - __half2float(h));
    g_wTh[n * 72 + k] = h;
    g_wTl[n * 72 + k] = l;
}

// ---------------- QK projection GEMM (legacy mma, pre-converted operands) ----------------
// Staging is now pure copies; MMA loop/epilogue identical to the verified R11.
__global__ void __launch_bounds__(512) gemm_qk_kernel(const float* __restrict__ b) {
    extern __shared__ char sm_raw[];
    __half* xs_h = (__half*)sm_raw;                       // [128][72]
    __half* xs_l = (__half*)(sm_raw + XS_BYTES);
    __half* ws_h = (__half*)(sm_raw + 2 * XS_BYTES);      // [256][72] = W^T
    __half* ws_l = (__half*)(sm_raw + 2 * XS_BYTES + WS_BYTES);
    const int tid = threadIdx.x;
    const int n0 = blockIdx.x * 128;

    // stage x halves: 128 rows x 8 uint4-chunks (8 halves each) per array
#pragma unroll
    for (int i = 0; i < 2; i++) {
        int task = tid + i * 512;            // 0..1023
        int r = task >> 3, c8 = task & 7;
        int n = n0 + r;
        uint4 vh = make_uint4(0u, 0u, 0u, 0u), vl = vh;
        if (n < NN) {
            vh = *(const uint4*)((const __half*)g_xh + (size_t)n * 64 + c8 * 8);
            vl = *(const uint4*)((const __half*)g_xl + (size_t)n * 64 + c8 * 8);
        }
        *(uint4*)(xs_h + r * 72 + c8 * 8) = vh;
        *(uint4*)(xs_l + r * 72 + c8 * 8) = vl;
    }
    // stage W^T halves: 2304 uint4 per array
    for (int i = tid; i < 2304; i += 512) {
        ((uint4*)ws_h)[i] = ((const uint4*)g_wTh)[i];
        ((uint4*)ws_l)[i] = ((const uint4*)g_wTl)[i];
    }
    __syncthreads();

    const int warp = tid >> 5, lane = tid & 31;
    const int wm = warp >> 1, wn = warp & 1;
    const int g = lane >> 2, t = lane & 3;
    const int rowb = wm * 16;

    float acc[16][4];
#pragma unroll
    for (int nt = 0; nt < 16; nt++) {
        int col0 = wn * 128 + nt * 8 + 2 * t;
        float2 bb = *(const float2*)(b + col0);
        acc[nt][0] = bb.x; acc[nt][1] = bb.y;
        acc[nt][2] = bb.x; acc[nt][3] = bb.y;
    }

#pragma unroll
    for (int ks = 0; ks < 4; ks++) {
        const int ka = ks * 16 + 2 * t;
        const int ra = (rowb + g) * 72, rb = (rowb + g + 8) * 72;
        uint32_t ah0 = *(const uint32_t*)&xs_h[ra + ka];
        uint32_t ah1 = *(const uint32_t*)&xs_h[rb + ka];
        uint32_t ah2 = *(const uint32_t*)&xs_h[ra + ka + 8];
        uint32_t ah3 = *(const uint32_t*)&xs_h[rb + ka + 8];
        uint32_t al0 = *(const uint32_t*)&xs_l[ra + ka];
        uint32_t al1 = *(const uint32_t*)&xs_l[rb + ka];
        uint32_t al2 = *(const uint32_t*)&xs_l[ra + ka + 8];
        uint32_t al3 = *(const uint32_t*)&xs_l[rb + ka + 8];
#pragma unroll
        for (int nt = 0; nt < 16; nt++) {
            int n = (wn * 128 + nt * 8 + g) * 72;
            uint32_t bh0 = *(const uint32_t*)&ws_h[n + ka];
            uint32_t bh1 = *(const uint32_t*)&ws_h[n + ka + 8];
            uint32_t bl0 = *(const uint32_t*)&ws_l[n + ka];
            uint32_t bl1 = *(const uint32_t*)&ws_l[n + ka + 8];
            MMA16816(acc[nt], ah0, ah1, ah2, ah3, bh0, bh1);
            MMA16816(acc[nt], ah0, ah1, ah2, ah3, bl0, bl1);
            MMA16816(acc[nt], al0, al1, al2, al3, bh0, bh1);
        }
    }

    const int nr0 = n0 + rowb + g;
    const int nr1 = nr0 + 8;
#pragma unroll
    for (int nt = 0; nt < 16; nt++) {
        int cl = nt * 8 + 2 * t;
        float* outbase = ((cl >> 6) & 1) ? g_k : g_q;
        int f = cl & 63;
        size_t off = (size_t)wn * 64 + f;
        if (nr0 < NN)
            *(float2*)(outbase + (size_t)nr0 * 128 + off) = make_float2(acc[nt][0], acc[nt][1]);
        if (nr1 < NN)
            *(float2*)(outbase + (size_t)nr1 * 128 + off) = make_float2(acc[nt][2], acc[nt][3]);
    }
}

// ---------------- fused edge scores + softmax + output (R11-proven) ----------------
__global__ void __launch_bounds__(256) edge_row_kernel(float* __restrict__ out) {
    __shared__ float2 exs[8][EX_CAP + 4];
    __shared__ int2   sse[8][EX_CAP];
    const int warp = threadIdx.x >> 5;
    const int lane = threadIdx.x & 31;
    const int r = blockIdx.x * 8 + warp;
    if (r >= NN) return;

    const int s0 = g_start[r];
    const int s1 = g_start[r + 1];
    const int deg = s1 - s0;
    if (deg == 0) return;

    const float4 qv = *(const float4*)(g_q + (size_t)r * 128 + lane * 4);
    const float4* kp = (const float4*)g_k;
    const bool head_lane = ((lane & 15) == 0);
    const int h = lane >> 4;
    float d = 0.0f;

    if (deg <= EX_CAP) {
        for (int j = lane; j < deg; j += 32) sse[warp][j] = g_sedge[s0 + j];
        __syncwarp();

        int pos = 0;
        const int qend = deg & ~3;
        for (; pos < qend; pos += 4) {
            int c0 = sse[warp][pos].x,     c1 = sse[warp][pos + 1].x;
            int c2 = sse[warp][pos + 2].x, c3 = sse[warp][pos + 3].x;
            float4 k0 = __ldg(kp + c0 * 32 + lane);
            float4 k1 = __ldg(kp + c1 * 32 + lane);
            float4 k2 = __ldg(kp + c2 * 32 + lane);
            float4 k3 = __ldg(kp + c3 * 32 + lane);
            float p0 = qv.x * k0.x + qv.y * k0.y + qv.z * k0.z + qv.w * k0.w;
            float p1 = qv.x * k1.x + qv.y * k1.y + qv.z * k1.z + qv.w * k1.w;
            float p2 = qv.x * k2.x + qv.y * k2.y + qv.z * k2.z + qv.w * k2.w;
            float p3 = qv.x * k3.x + qv.y * k3.y + qv.z * k3.z + qv.w * k3.w;
#pragma unroll
            for (int off = 8; off >= 1; off >>= 1) {
                p0 += __shfl_xor_sync(0xffffffffu, p0, off);
                p1 += __shfl_xor_sync(0xffffffffu, p1, off);
                p2 += __shfl_xor_sync(0xffffffffu, p2, off);
                p3 += __shfl_xor_sync(0xffffffffu, p3, off);
            }
            if (head_lane) {
                float v0 = __expf(p0), v1 = __expf(p1);
                float v2 = __expf(p2), v3 = __expf(p3);
                ((float*)&exs[warp][pos + 0])[h] = v0;
                ((float*)&exs[warp][pos + 1])[h] = v1;
                ((float*)&exs[warp][pos + 2])[h] = v2;
                ((float*)&exs[warp][pos + 3])[h] = v3;
                d += (v0 + v1) + (v2 + v3);
            }
        }
        for (; pos < deg; pos++) {
            int c0 = sse[warp][pos].x;
            float4 k0 = __ldg(kp + c0 * 32 + lane);
            float p0 = qv.x * k0.x + qv.y * k0.y + qv.z * k0.z + qv.w * k0.w;
#pragma unroll
            for (int off = 8; off >= 1; off >>= 1)
                p0 += __shfl_xor_sync(0xffffffffu, p0, off);
            if (head_lane) {
                float v0 = __expf(p0);
                ((float*)&exs[warp][pos])[h] = v0;
                d += v0;
            }
        }
        float D0 = __shfl_sync(0xffffffffu, d, 0);
        float D1 = __shfl_sync(0xffffffffu, d, 16);
        float i0 = 0.5f / D0, i1 = 0.5f / D1;
        __syncwarp();
        for (int j = lane; j < deg; j += 32) {
            float2 e = exs[warp][j];
            out[sse[warp][j].y] = e.x * i0 + e.y * i1;
        }
    } else {
        for (int posg = s0; posg < s1; posg++) {
            int2 e0 = g_sedge[posg];
            float4 k0 = __ldg(kp + e0.x * 32 + lane);
            float p0 = qv.x * k0.x + qv.y * k0.y + qv.z * k0.z + qv.w * k0.w;
#pragma unroll
            for (int off = 8; off >= 1; off >>= 1)
                p0 += __shfl_xor_sync(0xffffffffu, p0, off);
            if (head_lane) {
                float v0 = __expf(p0);
                g_ex2[2 * (size_t)posg + h] = v0;
                d += v0;
            }
        }
        float D0 = __shfl_sync(0xffffffffu, d, 0);
        float D1 = __shfl_sync(0xffffffffu, d, 16);
        float i0 = 0.5f / D0, i1 = 0.5f / D1;
        __syncwarp();
        for (int j = lane; j < deg; j += 32) {
            float2 e = *(const float2*)(g_ex2 + 2 * (size_t)(s0 + j));
            out[g_sedge[s0 + j].y] = e.x * i0 + e.y * i1;
        }
    }
}

extern "C" void kernel_launch(void* const* d_in, const int* in_sizes, int n_in,
                              void* d_out, int out_size) {
    const float* x    = (const float*)d_in[0];
    const float* W_qk = (const float*)d_in[1];
    const float* b_qk = (const float*)d_in[2];
    const int*   ei   = (const int*)d_in[3];   // [2, E] row-major
    const int* row = ei;
    const int* col = ei + EE;
    float* out = (float*)d_out;

    cudaFuncSetAttribute(gemm_qk_kernel,
                         cudaFuncAttributeMaxDynamicSharedMemorySize, GEMM_SMEM);

    // Fork: conversion + GEMM chain on s2 (submitted first), overlapping the
    // sort chain on stream 0 in the captured graph.
    cudaStream_t s2;
    cudaEvent_t evFork, evJoin;
    cudaStreamCreateWithFlags(&s2, cudaStreamNonBlocking);
    cudaEventCreateWithFlags(&evFork, cudaEventDisableTiming);
    cudaEventCreateWithFlags(&evJoin, cudaEventDisableTiming);

    cudaEventRecord(evFork, 0);
    cudaStreamWaitEvent(s2, evFork, 0);

    xconv_kernel<<<(NN * 16 + 255) / 256, 256, 0, s2>>>(x);
    wconv_kernel<<<(64 * 256 + 255) / 256, 256, 0, s2>>>(W_qk);
    gemm_qk_kernel<<<(NN + 127) / 128, 512, GEMM_SMEM, s2>>>(b_qk);
    cudaEventRecord(evJoin, s2);

    hist_kernel<<<(EE / 4 + 255) / 256, 256>>>((const int4*)row);
    scan_lb_kernel<<<SCAN_BLOCKS, 256>>>();
    scatter_kernel<<<(EE + 255) / 256, 256>>>(row, col);

    cudaStreamWaitEvent(0, evJoin, 0);
    edge_row_kernel<<<(NN + 7) / 8, 256>>>(out);
}

// round 17
// speedup vs baseline: 1.2090x; 1.0253x over previous
#include <cuda_runtime.h>
#include <cuda_fp16.h>
#include <cstdint>

#define NN 50000
#define FF 64
#define EE 800000
#define SCAN_BLOCKS ((NN + 255) / 256)   // 196
#define EX_CAP 128
#define XS_BYTES (128 * 72 * 2)
#define WS_BYTES (256 * 72 * 2)
#define GEMM_SMEM (2 * XS_BYTES + 2 * WS_BYTES)   // 110592

// Scratch (static __device__ — zero-initialized at load; kernels restore their
// scratch to zero each execution so graph replays are deterministic)
__device__ float        g_q[(size_t)NN * 128];    // [N][h*64+f]
__device__ float        g_k[(size_t)NN * 128];
__device__ int          g_hist[NN];
__device__ int          g_start[NN + 1];
__device__ unsigned int g_state[SCAN_BLOCKS];     // lookback: (sum<<2)|status
__device__ int          g_rank[EE];               // edge's position within its row
__device__ int2         g_sedge[EE];              // (col, orig edge id) row-sorted
__device__ float        g_ex2[(size_t)EE * 2];    // fallback exp storage (deg > EX_CAP)
// pre-converted fp16 hi/lo operands (written each run by xconv/wconv)
__device__ __half       g_xh[(size_t)NN * 64];
__device__ __half       g_xl[(size_t)NN * 64];
__device__ __half       g_wTh[256 * 72];          // W^T padded [n][k]
__device__ __half       g_wTl[256 * 72];

#define MMA16816(d, a0, a1, a2, a3, b0, b1) \
    asm volatile("mma.sync.aligned.m16n8k16.row.col.f32.f16.f16.f32 " \
        "{%0,%1,%2,%3}, {%4,%5,%6,%7}, {%8,%9}, {%0,%1,%2,%3};" \
        : "+f"((d)[0]), "+f"((d)[1]), "+f"((d)[2]), "+f"((d)[3]) \
        : "r"(a0), "r"(a1), "r"(a2), "r"(a3), "r"(b0), "r"(b1))

// ---------------- counting sort of edges by row ----------------

// Histogram WITH rank capture: the atomic return (already paid) becomes the
// edge's position within its row, stored coalesced -> scatter needs no atomic.
__global__ void __launch_bounds__(256) histrank_kernel(const int* __restrict__ row) {
    int e = blockIdx.x * blockDim.x + threadIdx.x;
    if (e < EE) g_rank[e] = atomicAdd(&g_hist[row[e]], 1);
}

__global__ void scan_lb_kernel() {
    __shared__ int sh[256];
    __shared__ int s_exc;
    const int t = threadIdx.x;
    const int bid = blockIdx.x;
    const int i = bid * 256 + t;
    int v = 0;
    if (i < NN) { v = g_hist[i]; g_hist[i] = 0; }
    sh[t] = v;
    __syncthreads();
#pragma unroll
    for (int off = 1; off < 256; off <<= 1) {
        int u = (t >= off) ? sh[t - off] : 0;
        __syncthreads();
        sh[t] += u;
        __syncthreads();
    }
    const int blockAgg = sh[255];
    if (t == 0) {
        if (bid == 0) {
            atomicExch(&g_state[0], ((unsigned)blockAgg << 2) | 2u);
            s_exc = 0;
        } else {
            atomicExch(&g_state[bid], ((unsigned)blockAgg << 2) | 1u);
            int exc = 0;
            int p = bid - 1;
            while (true) {
                unsigned st;
                do { st = atomicOr(&g_state[p], 0u); } while ((st & 3u) == 0u);
                exc += (int)(st >> 2);
                if ((st & 3u) == 2u) break;
                p--;
            }
            atomicExch(&g_state[bid], ((unsigned)(exc + blockAgg) << 2) | 2u);
            s_exc = exc;
        }
    }
    __syncthreads();
    const int base = s_exc;
    if (i < NN) g_start[i] = sh[t] - v + base;   // exclusive
    if (i == 0) g_start[NN] = EE;
}

// Atomic-free scatter: position is start[row] + precomputed rank.
__global__ void __launch_bounds__(256) scatter_kernel(const int* __restrict__ row,
                                                      const int* __restrict__ col) {
    if (blockIdx.x == 0 && threadIdx.x < SCAN_BLOCKS) g_state[threadIdx.x] = 0u;
    int e = blockIdx.x * blockDim.x + threadIdx.x;
    if (e >= EE) return;
    int r = row[e];
    int pos = g_start[r] + g_rank[e];
    g_sedge[pos] = make_int2(col[e], e);
}

// ---------------- one-time operand conversion (hoisted out of gemm) ----------------

__global__ void __launch_bounds__(256) xconv_kernel(const float* __restrict__ x) {
    int i = blockIdx.x * blockDim.x + threadIdx.x;   // float4 index
    if (i >= NN * 16) return;
    float4 v = __ldg((const float4*)x + i);
    float f[4] = {v.x, v.y, v.z, v.w};
    ushort2 hi2[2], lo2[2];
#pragma unroll
    for (int j = 0; j < 2; j++) {
        __half h0 = __float2half_rn(f[2 * j]);
        __half h1 = __float2half_rn(f[2 * j + 1]);
        __half l0 = __float2half_rn(f[2 * j] - __half2float(h0));
        __half l1 = __float2half_rn(f[2 * j + 1] - __half2float(h1));
        hi2[j] = make_ushort2(__half_as_ushort(h0), __half_as_ushort(h1));
        lo2[j] = make_ushort2(__half_as_ushort(l0), __half_as_ushort(l1));
    }
    *(uint2*)((__half*)g_xh + (size_t)i * 4) = *(uint2*)hi2;
    *(uint2*)((__half*)g_xl + (size_t)i * 4) = *(uint2*)lo2;
}

__global__ void __launch_bounds__(256) wconv_kernel(const float* __restrict__ W) {
    int i = blockIdx.x * blockDim.x + threadIdx.x;
    if (i >= 64 * 256) return;
    int k = i >> 8, n = i & 255;
    float f = __ldg(W + k * 256 + n);
    __half h = __float2half_rn(f);
    __half l = __float2half_rn(f - __half2float(h));
    g_wTh[n * 72 + k] = h;
    g_wTl[n * 72 + k] = l;
}

// ---------------- QK projection GEMM (legacy mma, pre-converted operands) ----------------
__global__ void __launch_bounds__(512) gemm_qk_kernel(const float* __restrict__ b) {
    extern __shared__ char sm_raw[];
    __half* xs_h = (__half*)sm_raw;                       // [128][72]
    __half* xs_l = (__half*)(sm_raw + XS_BYTES);
    __half* ws_h = (__half*)(sm_raw + 2 * XS_BYTES);      // [256][72] = W^T
    __half* ws_l = (__half*)(sm_raw + 2 * XS_BYTES + WS_BYTES);
    const int tid = threadIdx.x;
    const int n0 = blockIdx.x * 128;

#pragma unroll
    for (int i = 0; i < 2; i++) {
        int task = tid + i * 512;            // 0..1023
        int r = task >> 3, c8 = task & 7;
        int n = n0 + r;
        uint4 vh = make_uint4(0u, 0u, 0u, 0u), vl = vh;
        if (n < NN) {
            vh = *(const uint4*)((const __half*)g_xh + (size_t)n * 64 + c8 * 8);
            vl = *(const uint4*)((const __half*)g_xl + (size_t)n * 64 + c8 * 8);
        }
        *(uint4*)(xs_h + r * 72 + c8 * 8) = vh;
        *(uint4*)(xs_l + r * 72 + c8 * 8) = vl;
    }
    for (int i = tid; i < 2304; i += 512) {
        ((uint4*)ws_h)[i] = ((const uint4*)g_wTh)[i];
        ((uint4*)ws_l)[i] = ((const uint4*)g_wTl)[i];
    }
    __syncthreads();

    const int warp = tid >> 5, lane = tid & 31;
    const int wm = warp >> 1, wn = warp & 1;
    const int g = lane >> 2, t = lane & 3;
    const int rowb = wm * 16;

    float acc[16][4];
#pragma unroll
    for (int nt = 0; nt < 16; nt++) {
        int col0 = wn * 128 + nt * 8 + 2 * t;
        float2 bb = *(const float2*)(b + col0);
        acc[nt][0] = bb.x; acc[nt][1] = bb.y;
        acc[nt][2] = bb.x; acc[nt][3] = bb.y;
    }

#pragma unroll
    for (int ks = 0; ks < 4; ks++) {
        const int ka = ks * 16 + 2 * t;
        const int ra = (rowb + g) * 72, rb = (rowb + g + 8) * 72;
        uint32_t ah0 = *(const uint32_t*)&xs_h[ra + ka];
        uint32_t ah1 = *(const uint32_t*)&xs_h[rb + ka];
        uint32_t ah2 = *(const uint32_t*)&xs_h[ra + ka + 8];
        uint32_t ah3 = *(const uint32_t*)&xs_h[rb + ka + 8];
        uint32_t al0 = *(const uint32_t*)&xs_l[ra + ka];
        uint32_t al1 = *(const uint32_t*)&xs_l[rb + ka];
        uint32_t al2 = *(const uint32_t*)&xs_l[ra + ka + 8];
        uint32_t al3 = *(const uint32_t*)&xs_l[rb + ka + 8];
#pragma unroll
        for (int nt = 0; nt < 16; nt++) {
            int n = (wn * 128 + nt * 8 + g) * 72;
            uint32_t bh0 = *(const uint32_t*)&ws_h[n + ka];
            uint32_t bh1 = *(const uint32_t*)&ws_h[n + ka + 8];
            uint32_t bl0 = *(const uint32_t*)&ws_l[n + ka];
            uint32_t bl1 = *(const uint32_t*)&ws_l[n + ka + 8];
            MMA16816(acc[nt], ah0, ah1, ah2, ah3, bh0, bh1);
            MMA16816(acc[nt], ah0, ah1, ah2, ah3, bl0, bl1);
            MMA16816(acc[nt], al0, al1, al2, al3, bh0, bh1);
        }
    }

    const int nr0 = n0 + rowb + g;
    const int nr1 = nr0 + 8;
#pragma unroll
    for (int nt = 0; nt < 16; nt++) {
        int cl = nt * 8 + 2 * t;
        float* outbase = ((cl >> 6) & 1) ? g_k : g_q;
        int f = cl & 63;
        size_t off = (size_t)wn * 64 + f;
        if (nr0 < NN)
            *(float2*)(outbase + (size_t)nr0 * 128 + off) = make_float2(acc[nt][0], acc[nt][1]);
        if (nr1 < NN)
            *(float2*)(outbase + (size_t)nr1 * 128 + off) = make_float2(acc[nt][2], acc[nt][3]);
    }
}

// ---------------- fused edge scores + softmax + output (R11-proven) ----------------
__global__ void __launch_bounds__(256) edge_row_kernel(float* __restrict__ out) {
    __shared__ float2 exs[8][EX_CAP + 4];
    __shared__ int2   sse[8][EX_CAP];
    const int warp = threadIdx.x >> 5;
    const int lane = threadIdx.x & 31;
    const int r = blockIdx.x * 8 + warp;
    if (r >= NN) return;

    const int s0 = g_start[r];
    const int s1 = g_start[r + 1];
    const int deg = s1 - s0;
    if (deg == 0) return;

    const float4 qv = *(const float4*)(g_q + (size_t)r * 128 + lane * 4);
    const float4* kp = (const float4*)g_k;
    const bool head_lane = ((lane & 15) == 0);
    const int h = lane >> 4;
    float d = 0.0f;

    if (deg <= EX_CAP) {
        for (int j = lane; j < deg; j += 32) sse[warp][j] = g_sedge[s0 + j];
        __syncwarp();

        int pos = 0;
        const int qend = deg & ~3;
        for (; pos < qend; pos += 4) {
            int c0 = sse[warp][pos].x,     c1 = sse[warp][pos + 1].x;
            int c2 = sse[warp][pos + 2].x, c3 = sse[warp][pos + 3].x;
            float4 k0 = __ldg(kp + c0 * 32 + lane);
            float4 k1 = __ldg(kp + c1 * 32 + lane);
            float4 k2 = __ldg(kp + c2 * 32 + lane);
            float4 k3 = __ldg(kp + c3 * 32 + lane);
            float p0 = qv.x * k0.x + qv.y * k0.y + qv.z * k0.z + qv.w * k0.w;
            float p1 = qv.x * k1.x + qv.y * k1.y + qv.z * k1.z + qv.w * k1.w;
            float p2 = qv.x * k2.x + qv.y * k2.y + qv.z * k2.z + qv.w * k2.w;
            float p3 = qv.x * k3.x + qv.y * k3.y + qv.z * k3.z + qv.w * k3.w;
#pragma unroll
            for (int off = 8; off >= 1; off >>= 1) {
                p0 += __shfl_xor_sync(0xffffffffu, p0, off);
                p1 += __shfl_xor_sync(0xffffffffu, p1, off);
                p2 += __shfl_xor_sync(0xffffffffu, p2, off);
                p3 += __shfl_xor_sync(0xffffffffu, p3, off);
            }
            if (head_lane) {
                float v0 = __expf(p0), v1 = __expf(p1);
                float v2 = __expf(p2), v3 = __expf(p3);
                ((float*)&exs[warp][pos + 0])[h] = v0;
                ((float*)&exs[warp][pos + 1])[h] = v1;
                ((float*)&exs[warp][pos + 2])[h] = v2;
                ((float*)&exs[warp][pos + 3])[h] = v3;
                d += (v0 + v1) + (v2 + v3);
            }
        }
        for (; pos < deg; pos++) {
            int c0 = sse[warp][pos].x;
            float4 k0 = __ldg(kp + c0 * 32 + lane);
            float p0 = qv.x * k0.x + qv.y * k0.y + qv.z * k0.z + qv.w * k0.w;
#pragma unroll
            for (int off = 8; off >= 1; off >>= 1)
                p0 += __shfl_xor_sync(0xffffffffu, p0, off);
            if (head_lane) {
                float v0 = __expf(p0);
                ((float*)&exs[warp][pos])[h] = v0;
                d += v0;
            }
        }
        float D0 = __shfl_sync(0xffffffffu, d, 0);
        float D1 = __shfl_sync(0xffffffffu, d, 16);
        float i0 = 0.5f / D0, i1 = 0.5f / D1;
        __syncwarp();
        for (int j = lane; j < deg; j += 32) {
            float2 e = exs[warp][j];
            out[sse[warp][j].y] = e.x * i0 + e.y * i1;
        }
    } else {
        for (int posg = s0; posg < s1; posg++) {
            int2 e0 = g_sedge[posg];
            float4 k0 = __ldg(kp + e0.x * 32 + lane);
            float p0 = qv.x * k0.x + qv.y * k0.y + qv.z * k0.z + qv.w * k0.w;
#pragma unroll
            for (int off = 8; off >= 1; off >>= 1)
                p0 += __shfl_xor_sync(0xffffffffu, p0, off);
            if (head_lane) {
                float v0 = __expf(p0);
                g_ex2[2 * (size_t)posg + h] = v0;
                d += v0;
            }
        }
        float D0 = __shfl_sync(0xffffffffu, d, 0);
        float D1 = __shfl_sync(0xffffffffu, d, 16);
        float i0 = 0.5f / D0, i1 = 0.5f / D1;
        __syncwarp();
        for (int j = lane; j < deg; j += 32) {
            float2 e = *(const float2*)(g_ex2 + 2 * (size_t)(s0 + j));
            out[g_sedge[s0 + j].y] = e.x * i0 + e.y * i1;
        }
    }
}

extern "C" void kernel_launch(void* const* d_in, const int* in_sizes, int n_in,
                              void* d_out, int out_size) {
    const float* x    = (const float*)d_in[0];
    const float* W_qk = (const float*)d_in[1];
    const float* b_qk = (const float*)d_in[2];
    const int*   ei   = (const int*)d_in[3];   // [2, E] row-major
    const int* row = ei;
    const int* col = ei + EE;
    float* out = (float*)d_out;

    cudaFuncSetAttribute(gemm_qk_kernel,
                         cudaFuncAttributeMaxDynamicSharedMemorySize, GEMM_SMEM);

    // Fork: conversion + GEMM chain on s2 (submitted first), overlapping the
    // sort chain on stream 0 in the captured graph.
    cudaStream_t s2;
    cudaEvent_t evFork, evJoin;
    cudaStreamCreateWithFlags(&s2, cudaStreamNonBlocking);
    cudaEventCreateWithFlags(&evFork, cudaEventDisableTiming);
    cudaEventCreateWithFlags(&evJoin, cudaEventDisableTiming);

    cudaEventRecord(evFork, 0);
    cudaStreamWaitEvent(s2, evFork, 0);

    xconv_kernel<<<(NN * 16 + 255) / 256, 256, 0, s2>>>(x);
    wconv_kernel<<<(64 * 256 + 255) / 256, 256, 0, s2>>>(W_qk);
    gemm_qk_kernel<<<(NN + 127) / 128, 512, GEMM_SMEM, s2>>>(b_qk);
    cudaEventRecord(evJoin, s2);

    histrank_kernel<<<(EE + 255) / 256, 256>>>(row);
    scan_lb_kernel<<<SCAN_BLOCKS, 256>>>();
    scatter_kernel<<<(EE + 255) / 256, 256>>>(row, col);

    cudaStreamWaitEvent(0, evJoin, 0);
    edge_row_kernel<<<(NN + 7) / 8, 256>>>(out);
}